// round 5
// baseline (speedup 1.0000x reference)
#include <cuda_runtime.h>
#include <cstdint>
#include <math.h>

// ---------------- problem constants ----------------
#define NE      8
#define TPE     2048
#define DMODEL  1024
#define DFF     4096

// ---------------- tiling ----------------
#define BM      128
#define BN      128
#define BK      32
#define STAGES  3
#define NT      256      // 8 warps: 4 (M) x 2 (N); warp tile 32 x 64
#define STRIDE  36       // smem row pitch in floats (32 + 4 pad) -> conflict-free LDSM/STS
#define MI      2
#define NI      8

// ---------------- device scratch (no runtime allocation) ----------------
__device__ float g_x  [(size_t)NE * TPE * DMODEL];   // tf32-rounded x
__device__ float g_h  [(size_t)NE * TPE * DFF];      // gelu(x@w1+b1), tf32-rounded
__device__ float g_w1t[(size_t)NE * DMODEL * DFF];   // w1^T per expert: [F, D], rounded
__device__ float g_w2t[(size_t)NE * DMODEL * DFF];   // w2^T per expert: [D, F], rounded

// ---------------- helpers ----------------
__device__ __forceinline__ uint32_t smem_u32(const void* p) {
    return (uint32_t)__cvta_generic_to_shared(p);
}
__device__ __forceinline__ void cp_async16(uint32_t dst, const void* src) {
    asm volatile("cp.async.cg.shared.global [%0], [%1], 16;\n" ::"r"(dst), "l"(src));
}
__device__ __forceinline__ float tf32r(float f) {   // round-to-nearest tf32, kept as f32
    uint32_t u;
    asm("cvt.rna.tf32.f32 %0, %1;\n" : "=r"(u) : "f"(f));
    return __uint_as_float(u);
}
__device__ __forceinline__ void ldmatrix_x4(uint32_t r[4], uint32_t addr) {
    asm volatile("ldmatrix.sync.aligned.m8n8.x4.shared.b16 {%0,%1,%2,%3}, [%4];\n"
                 : "=r"(r[0]), "=r"(r[1]), "=r"(r[2]), "=r"(r[3])
                 : "r"(addr));
}
__device__ __forceinline__ void mma_tf32(float c[4], const uint32_t a[4],
                                         uint32_t b0, uint32_t b1) {
    asm volatile(
        "mma.sync.aligned.m16n8k8.row.col.f32.tf32.tf32.f32 "
        "{%0,%1,%2,%3}, {%4,%5,%6,%7}, {%8,%9}, {%0,%1,%2,%3};\n"
        : "+f"(c[0]), "+f"(c[1]), "+f"(c[2]), "+f"(c[3])
        : "r"(a[0]), "r"(a[1]), "r"(a[2]), "r"(a[3]), "r"(b0), "r"(b1));
}
__device__ __forceinline__ float gelu_tanh(float x) {   // jax.nn.gelu (tanh form)
    float x3 = x * x * x;
    float t  = tanhf(0.7978845608028654f * (x + 0.044715f * x3));
    return 0.5f * x * (1.0f + t);
}

// ---------------- pre-passes ----------------
__global__ void round_x_k(const float* __restrict__ in, float* __restrict__ out, int n4) {
    int i = blockIdx.x * blockDim.x + threadIdx.x;
    if (i < n4) {
        float4 v = ((const float4*)in)[i];
        v.x = tf32r(v.x); v.y = tf32r(v.y); v.z = tf32r(v.z); v.w = tf32r(v.w);
        ((float4*)out)[i] = v;
    }
}
// per-expert transpose: in[e] (R x C) -> out[e] (C x R), tf32-rounded
__global__ void transpose_round_k(const float* __restrict__ in, float* __restrict__ out,
                                  int R, int C) {
    __shared__ float t[32][33];
    const float* ip = in  + (size_t)blockIdx.z * R * C;
    float*       op = out + (size_t)blockIdx.z * R * C;
    int r0 = blockIdx.y << 5, c0 = blockIdx.x << 5;
    int x = threadIdx.x & 31, y = threadIdx.x >> 5;
#pragma unroll
    for (int j = 0; j < 4; j++)
        t[y + j * 8][x] = ip[(size_t)(r0 + y + j * 8) * C + c0 + x];
    __syncthreads();
#pragma unroll
    for (int j = 0; j < 4; j++)
        op[(size_t)(c0 + y + j * 8) * R + r0 + x] = tf32r(t[x][y + j * 8]);
}

// ---------------- grouped GEMM: C = act(A @ Bt^T + bias) ----------------
// A:  [E*TPE, K] row-major (K-major), tf32-pre-rounded.
// Bt: per expert [N, K] (K-major), pre-transposed + rounded.
// Inner loop is software-pipelined at the fragment level: every ldmatrix is
// issued one consumer-group ahead, covered by ~16 MMA issues (asm volatile
// keeps the written order).
template <bool GELU>
__global__ void __launch_bounds__(NT, 2)
moe_gemm(const float* __restrict__ Ag, const float* __restrict__ Btg,
         const float* __restrict__ biasg, float* __restrict__ Cg,
         int K, int N)
{
    extern __shared__ float smem[];
    const int e = blockIdx.z, by = blockIdx.y, bx = blockIdx.x;
    const int tid = threadIdx.x, lane = tid & 31, warp = tid >> 5;
    const int wm = warp & 3;    // warp row (M)
    const int wn = warp >> 2;   // warp col (N)

    const float* A    = Ag    + (size_t)(e * TPE + by * BM) * K;
    const float* Bt   = Btg   + (size_t)e * K * N + (size_t)(bx * BN) * K;
    const float* bias = biasg + (size_t)e * N + (size_t)bx * BN;
    float*       C    = Cg    + (size_t)(e * TPE + by * BM) * N + (size_t)bx * BN;

    float* As_all = smem;                              // STAGES * BM * STRIDE
    float* Bs_all = smem + STAGES * (BM * STRIDE);     // STAGES * BN * STRIDE

    // cp.async: each tile 128 rows x 32 floats = 1024 x 16B chunks; 256 threads,
    // 4 threads per row (2 chunks each), rows r and r+64.
    const int ld_r = tid >> 2, ld_c = (tid & 3) * 8;

    float acc[MI][NI][4];
#pragma unroll
    for (int mi = 0; mi < MI; mi++)
#pragma unroll
        for (int ni = 0; ni < NI; ni++)
#pragma unroll
            for (int i = 0; i < 4; i++) acc[mi][ni][i] = 0.f;

    const int KT = K / BK;

    auto load_stage = [&](int kt, int s) {
        const float* Ak  = A  + kt * BK;
        const float* Btk = Bt + kt * BK;
        float* As = As_all + s * (BM * STRIDE);
        float* Bs = Bs_all + s * (BN * STRIDE);
#pragma unroll
        for (int half = 0; half < 2; half++) {
            int r = ld_r + half * 64;
            cp_async16(smem_u32(As + r * STRIDE + ld_c),     Ak  + (size_t)r * K + ld_c);
            cp_async16(smem_u32(As + r * STRIDE + ld_c + 4), Ak  + (size_t)r * K + ld_c + 4);
            cp_async16(smem_u32(Bs + r * STRIDE + ld_c),     Btk + (size_t)r * K + ld_c);
            cp_async16(smem_u32(Bs + r * STRIDE + ld_c + 4), Btk + (size_t)r * K + ld_c + 4);
        }
    };

#pragma unroll
    for (int s = 0; s < STAGES - 1; s++) {
        load_stage(s, s);
        asm volatile("cp.async.commit_group;\n");
    }

    // per-warp fragment base offsets (bytes), constant across kt
    const uint32_t a_row = wm * 32 + (lane & 15);
    const uint32_t a_off = (a_row * STRIDE + (lane >> 4) * 4) * 4;
    const uint32_t b_row = wn * 64 + ((lane >> 4) & 1) * 8 + (lane & 7);
    const uint32_t b_off = (b_row * STRIDE + ((lane >> 3) & 1) * 4) * 4;
#define A_STEP (16 * STRIDE * 4)   // +16 rows (next m16 tile)
#define B_STEP (16 * STRIDE * 4)   // +16 rows (next nj pair)
#define K_STEP 32                  // +8 floats (next ks)

    for (int kt = 0; kt < KT; kt++) {
        asm volatile("cp.async.wait_group %0;\n" ::"n"(STAGES - 2));
        __syncthreads();

        int kn = kt + STAGES - 1;
        if (kn < KT) load_stage(kn, kn % STAGES);
        asm volatile("cp.async.commit_group;\n");

        const int s = kt % STAGES;
        const uint32_t a0 = smem_u32(As_all + s * (BM * STRIDE)) + a_off;
        const uint32_t b0 = smem_u32(Bs_all + s * (BN * STRIDE)) + b_off;

        uint32_t a_cur[MI][4], a_nxt[MI][4], b_cur[4], b_nxt[4];
        ldmatrix_x4(a_cur[0], a0);
        ldmatrix_x4(a_cur[1], a0 + A_STEP);
        ldmatrix_x4(b_cur, b0);

#pragma unroll
        for (int ks = 0; ks < BK / 8; ks++) {
#pragma unroll
            for (int nj = 0; nj < NI / 2; nj++) {
                // ---- prefetch (one group ahead), then consume ----
                if (nj < NI / 2 - 1) {
                    ldmatrix_x4(b_nxt, b0 + (nj + 1) * B_STEP + ks * K_STEP);
                } else if (ks < BK / 8 - 1) {
                    ldmatrix_x4(a_nxt[0], a0 + (ks + 1) * K_STEP);
                    ldmatrix_x4(a_nxt[1], a0 + A_STEP + (ks + 1) * K_STEP);
                    ldmatrix_x4(b_nxt, b0 + (ks + 1) * K_STEP);
                }
                mma_tf32(acc[0][2 * nj],     a_cur[0], b_cur[0], b_cur[1]);
                mma_tf32(acc[0][2 * nj + 1], a_cur[0], b_cur[2], b_cur[3]);
                mma_tf32(acc[1][2 * nj],     a_cur[1], b_cur[0], b_cur[1]);
                mma_tf32(acc[1][2 * nj + 1], a_cur[1], b_cur[2], b_cur[3]);
                if (nj < NI / 2 - 1 || ks < BK / 8 - 1) {
#pragma unroll
                    for (int i = 0; i < 4; i++) b_cur[i] = b_nxt[i];
                }
                if (nj == NI / 2 - 1 && ks < BK / 8 - 1) {
#pragma unroll
                    for (int mi = 0; mi < MI; mi++)
#pragma unroll
                        for (int i = 0; i < 4; i++) a_cur[mi][i] = a_nxt[mi][i];
                }
            }
        }
    }

    // ---------------- epilogue: bias (+GELU, tf32 round) ----------------
#pragma unroll
    for (int mi = 0; mi < MI; mi++) {
        int row = wm * 32 + mi * 16 + (lane >> 2);
#pragma unroll
        for (int ni = 0; ni < NI; ni++) {
            int col = wn * 64 + ni * 8 + (lane & 3) * 2;
            float bz0 = bias[col], bz1 = bias[col + 1];
            float v00 = acc[mi][ni][0] + bz0, v01 = acc[mi][ni][1] + bz1;
            float v10 = acc[mi][ni][2] + bz0, v11 = acc[mi][ni][3] + bz1;
            if (GELU) {   // h feeds GEMM2's A: round to tf32 here
                v00 = tf32r(gelu_tanh(v00)); v01 = tf32r(gelu_tanh(v01));
                v10 = tf32r(gelu_tanh(v10)); v11 = tf32r(gelu_tanh(v11));
            }
            *(float2*)(C + (size_t)row * N + col)       = make_float2(v00, v01);
            *(float2*)(C + (size_t)(row + 8) * N + col) = make_float2(v10, v11);
        }
    }
}

// ---------------- launch ----------------
extern "C" void kernel_launch(void* const* d_in, const int* in_sizes, int n_in,
                              void* d_out, int out_size)
{
    const float* x  = (const float*)d_in[0];
    const float* w1 = (const float*)d_in[2];
    const float* b1 = (const float*)d_in[3];
    const float* w2 = (const float*)d_in[4];
    const float* b2 = (const float*)d_in[5];
    float* y = (float*)d_out;

    float *xr, *h, *w1t, *w2t;
    cudaGetSymbolAddress((void**)&xr,  g_x);
    cudaGetSymbolAddress((void**)&h,   g_h);
    cudaGetSymbolAddress((void**)&w1t, g_w1t);
    cudaGetSymbolAddress((void**)&w2t, g_w2t);

    const int smem_bytes = STAGES * (BM * STRIDE + BN * STRIDE) * (int)sizeof(float);
    cudaFuncSetAttribute((const void*)moe_gemm<true>,
                         cudaFuncAttributeMaxDynamicSharedMemorySize, smem_bytes);
    cudaFuncSetAttribute((const void*)moe_gemm<false>,
                         cudaFuncAttributeMaxDynamicSharedMemorySize, smem_bytes);

    // pre-passes: round x; transpose + round weights to K-major [N, K]
    {
        int n4 = NE * TPE * DMODEL / 4;
        round_x_k<<<(n4 + 255) / 256, 256>>>(x, xr, n4);
        dim3 t1(DFF / 32, DMODEL / 32, NE);     // w1 [D,F] -> w1t [F,D]
        transpose_round_k<<<t1, 256>>>(w1, w1t, DMODEL, DFF);
        dim3 t2(DMODEL / 32, DFF / 32, NE);     // w2 [F,D] -> w2t [D,F]
        transpose_round_k<<<t2, 256>>>(w2, w2t, DFF, DMODEL);
    }

    dim3 blk(NT);
    // GEMM1: h = gelu(x @ w1 + b1)   per expert 2048x1024 @ 1024x4096
    dim3 g1(DFF / BN, TPE / BM, NE);
    moe_gemm<true><<<g1, blk, smem_bytes>>>(xr, w1t, b1, h, DMODEL, DFF);
    // GEMM2: y = h @ w2 + b2         per expert 2048x4096 @ 4096x1024
    dim3 g2(DMODEL / BN, TPE / BM, NE);
    moe_gemm<false><<<g2, blk, smem_bytes>>>(h, w2t, b2, y, DFF, DMODEL);
}

// round 6
// speedup vs baseline: 1.0535x; 1.0535x over previous
#include <cuda_runtime.h>
#include <cstdint>
#include <math.h>

// ---------------- problem constants ----------------
#define NE      8
#define TPE     2048
#define DMODEL  1024
#define DFF     4096

// ---------------- tiling ----------------
#define BM      128
#define BN      128
#define BK      32
#define STAGES  3
#define NT      256      // 8 warps: 4 (M) x 2 (N); warp tile 32 x 64
#define STRIDE  36       // smem row pitch in floats (32 + 4 pad) -> conflict-free LDSM/STS
#define MI      2
#define NI      8

// ---------------- device scratch (no runtime allocation) ----------------
__device__ float g_x  [(size_t)NE * TPE * DMODEL];   // tf32-rounded x
__device__ float g_h  [(size_t)NE * TPE * DFF];      // gelu(x@w1+b1), tf32-rounded
__device__ float g_w1t[(size_t)NE * DMODEL * DFF];   // w1^T per expert: [F, D], rounded
__device__ float g_w2t[(size_t)NE * DMODEL * DFF];   // w2^T per expert: [D, F], rounded

// ---------------- helpers ----------------
__device__ __forceinline__ uint32_t smem_u32(const void* p) {
    return (uint32_t)__cvta_generic_to_shared(p);
}
__device__ __forceinline__ void cp_async16(uint32_t dst, const void* src) {
    asm volatile("cp.async.cg.shared.global [%0], [%1], 16;\n" ::"r"(dst), "l"(src));
}
__device__ __forceinline__ float tf32r(float f) {   // round-to-nearest tf32, kept as f32
    uint32_t u;
    asm("cvt.rna.tf32.f32 %0, %1;\n" : "=r"(u) : "f"(f));
    return __uint_as_float(u);
}
__device__ __forceinline__ void ldmatrix_x4(uint32_t r[4], uint32_t addr) {
    asm volatile("ldmatrix.sync.aligned.m8n8.x4.shared.b16 {%0,%1,%2,%3}, [%4];\n"
                 : "=r"(r[0]), "=r"(r[1]), "=r"(r[2]), "=r"(r[3])
                 : "r"(addr));
}
__device__ __forceinline__ void mma_tf32(float c[4], const uint32_t a[4],
                                         uint32_t b0, uint32_t b1) {
    asm volatile(
        "mma.sync.aligned.m16n8k8.row.col.f32.tf32.tf32.f32 "
        "{%0,%1,%2,%3}, {%4,%5,%6,%7}, {%8,%9}, {%0,%1,%2,%3};\n"
        : "+f"(c[0]), "+f"(c[1]), "+f"(c[2]), "+f"(c[3])
        : "r"(a[0]), "r"(a[1]), "r"(a[2]), "r"(a[3]), "r"(b0), "r"(b1));
}
__device__ __forceinline__ float gelu_tanh(float x) {   // jax.nn.gelu (tanh form)
    float x3 = x * x * x;
    float t  = tanhf(0.7978845608028654f * (x + 0.044715f * x3));
    return 0.5f * x * (1.0f + t);
}

// ---------------- pre-passes ----------------
__global__ void round_x_k(const float* __restrict__ in, float* __restrict__ out, int n4) {
    int i = blockIdx.x * blockDim.x + threadIdx.x;
    if (i < n4) {
        float4 v = ((const float4*)in)[i];
        v.x = tf32r(v.x); v.y = tf32r(v.y); v.z = tf32r(v.z); v.w = tf32r(v.w);
        ((float4*)out)[i] = v;
    }
}
// per-expert transpose: in[e] (R x C) -> out[e] (C x R), tf32-rounded
__global__ void transpose_round_k(const float* __restrict__ in, float* __restrict__ out,
                                  int R, int C) {
    __shared__ float t[32][33];
    const float* ip = in  + (size_t)blockIdx.z * R * C;
    float*       op = out + (size_t)blockIdx.z * R * C;
    int r0 = blockIdx.y << 5, c0 = blockIdx.x << 5;
    int x = threadIdx.x & 31, y = threadIdx.x >> 5;
#pragma unroll
    for (int j = 0; j < 4; j++)
        t[y + j * 8][x] = ip[(size_t)(r0 + y + j * 8) * C + c0 + x];
    __syncthreads();
#pragma unroll
    for (int j = 0; j < 4; j++)
        op[(size_t)(c0 + y + j * 8) * R + r0 + x] = tf32r(t[x][y + j * 8]);
}

// ---------------- grouped GEMM: C = act(A @ Bt^T + bias) ----------------
// A:  [E*TPE, K] row-major (K-major), tf32-pre-rounded.
// Bt: per expert [N, K] (K-major), pre-transposed + rounded.
//
// Pipelining scheme (no register moves, parity-indexed double buffers):
//  - A frags double-buffered by ks parity, B frags by nj parity.
//  - At the TAIL of each kt (ks=3), the first fragments of kt+1 are loaded
//    from stage (kt+1)%3 BEFORE the barrier (data resident since kt-1, and
//    wait_group(0) at the top of kt guarantees its cp.async completed).
//    Registers survive the barrier -> MMAs restart immediately after sync.
#define A_STEP (16 * STRIDE * 4)   // +16 rows (next m16 tile), bytes
#define B_STEP (16 * STRIDE * 4)   // +16 rows (next nj pair), bytes
#define K_STEP 32                  // +8 floats (next ks), bytes

template <bool GELU>
__global__ void __launch_bounds__(NT, 2)
moe_gemm(const float* __restrict__ Ag, const float* __restrict__ Btg,
         const float* __restrict__ biasg, float* __restrict__ Cg,
         int K, int N)
{
    extern __shared__ float smem[];
    const int e = blockIdx.z, by = blockIdx.y, bx = blockIdx.x;
    const int tid = threadIdx.x, lane = tid & 31, warp = tid >> 5;
    const int wm = warp & 3;    // warp row (M)
    const int wn = warp >> 2;   // warp col (N)

    const float* A    = Ag    + (size_t)(e * TPE + by * BM) * K;
    const float* Bt   = Btg   + (size_t)e * K * N + (size_t)(bx * BN) * K;
    const float* bias = biasg + (size_t)e * N + (size_t)bx * BN;
    float*       C    = Cg    + (size_t)(e * TPE + by * BM) * N + (size_t)bx * BN;

    float* As_all = smem;                              // STAGES * BM * STRIDE
    float* Bs_all = smem + STAGES * (BM * STRIDE);     // STAGES * BN * STRIDE

    // cp.async: each tile 128 rows x 32 floats = 1024 x 16B chunks; 256 threads,
    // 4 threads per row (2 chunks each), rows r and r+64.
    const int ld_r = tid >> 2, ld_c = (tid & 3) * 8;

    float acc[MI][NI][4];
#pragma unroll
    for (int mi = 0; mi < MI; mi++)
#pragma unroll
        for (int ni = 0; ni < NI; ni++)
#pragma unroll
            for (int i = 0; i < 4; i++) acc[mi][ni][i] = 0.f;

    const int KT = K / BK;

    auto load_stage = [&](int kt, int s) {
        const float* Ak  = A  + kt * BK;
        const float* Btk = Bt + kt * BK;
        float* As = As_all + s * (BM * STRIDE);
        float* Bs = Bs_all + s * (BN * STRIDE);
#pragma unroll
        for (int half = 0; half < 2; half++) {
            int r = ld_r + half * 64;
            cp_async16(smem_u32(As + r * STRIDE + ld_c),     Ak  + (size_t)r * K + ld_c);
            cp_async16(smem_u32(As + r * STRIDE + ld_c + 4), Ak  + (size_t)r * K + ld_c + 4);
            cp_async16(smem_u32(Bs + r * STRIDE + ld_c),     Btk + (size_t)r * K + ld_c);
            cp_async16(smem_u32(Bs + r * STRIDE + ld_c + 4), Btk + (size_t)r * K + ld_c + 4);
        }
    };

    // per-warp fragment base offsets (bytes), constant across kt
    const uint32_t a_off = ((wm * 32 + (lane & 15)) * STRIDE + (lane >> 4) * 4) * 4;
    const uint32_t b_off =
        ((wn * 64 + ((lane >> 4) & 1) * 8 + (lane & 7)) * STRIDE + ((lane >> 3) & 1) * 4) * 4;

    // prologue: stages 0 and 1 in flight
    load_stage(0, 0);
    asm volatile("cp.async.commit_group;\n");
    load_stage(1, 1);
    asm volatile("cp.async.commit_group;\n");

    uint32_t a[2][MI][4];   // [ks parity][mi]
    uint32_t b[2][4];       // [nj parity]

    // stage 0 ready -> preload kt=0, ks=0 fragments
    asm volatile("cp.async.wait_group %0;\n" ::"n"(1));
    __syncthreads();
    {
        const uint32_t ca = smem_u32(As_all) + a_off;
        const uint32_t cb = smem_u32(Bs_all) + b_off;
        ldmatrix_x4(a[0][0], ca);
        ldmatrix_x4(a[0][1], ca + A_STEP);
        ldmatrix_x4(b[0], cb);
    }

    for (int kt = 0; kt < KT; kt++) {
        // stage kt+1 fully resident after this (needed by tail prefetch)
        asm volatile("cp.async.wait_group %0;\n" ::"n"(0));
        __syncthreads();   // all reads of stage (kt+2)%3 (== kt-1) finished

        int kn = kt + STAGES - 1;
        if (kn < KT) {
            load_stage(kn, kn % STAGES);
            asm volatile("cp.async.commit_group;\n");
        }

        const uint32_t ca = smem_u32(As_all + (kt % STAGES) * (BM * STRIDE)) + a_off;
        const uint32_t cb = smem_u32(Bs_all + (kt % STAGES) * (BN * STRIDE)) + b_off;
        const int ktn = (kt + 1 < KT) ? kt + 1 : kt;   // clamp: last tail prefetch harmless
        const uint32_t na = smem_u32(As_all + (ktn % STAGES) * (BM * STRIDE)) + a_off;
        const uint32_t nb = smem_u32(Bs_all + (ktn % STAGES) * (BN * STRIDE)) + b_off;

#pragma unroll
        for (int ks = 0; ks < BK / 8; ks++) {
#pragma unroll
            for (int nj = 0; nj < NI / 2; nj++) {
                // ---- prefetch one group ahead (parity regs, no moves) ----
                if (nj == 0) {
                    if (ks < BK / 8 - 1) {
                        ldmatrix_x4(a[(ks + 1) & 1][0], ca + (ks + 1) * K_STEP);
                        ldmatrix_x4(a[(ks + 1) & 1][1], ca + A_STEP + (ks + 1) * K_STEP);
                    } else {   // cross-barrier: next kt's ks=0 A pair
                        ldmatrix_x4(a[0][0], na);
                        ldmatrix_x4(a[0][1], na + A_STEP);
                    }
                }
                if (nj < NI / 2 - 1)
                    ldmatrix_x4(b[(nj + 1) & 1], cb + (nj + 1) * B_STEP + ks * K_STEP);
                else if (ks < BK / 8 - 1)
                    ldmatrix_x4(b[0], cb + (ks + 1) * K_STEP);
                else   // cross-barrier: next kt's ks=0, nj=0 B group
                    ldmatrix_x4(b[0], nb);

                // ---- consume current fragments ----
                mma_tf32(acc[0][2 * nj],     a[ks & 1][0], b[nj & 1][0], b[nj & 1][1]);
                mma_tf32(acc[0][2 * nj + 1], a[ks & 1][0], b[nj & 1][2], b[nj & 1][3]);
                mma_tf32(acc[1][2 * nj],     a[ks & 1][1], b[nj & 1][0], b[nj & 1][1]);
                mma_tf32(acc[1][2 * nj + 1], a[ks & 1][1], b[nj & 1][2], b[nj & 1][3]);
            }
        }
    }

    // ---------------- epilogue: bias (+GELU, tf32 round) ----------------
#pragma unroll
    for (int mi = 0; mi < MI; mi++) {
        int row = wm * 32 + mi * 16 + (lane >> 2);
#pragma unroll
        for (int ni = 0; ni < NI; ni++) {
            int col = wn * 64 + ni * 8 + (lane & 3) * 2;
            float bz0 = bias[col], bz1 = bias[col + 1];
            float v00 = acc[mi][ni][0] + bz0, v01 = acc[mi][ni][1] + bz1;
            float v10 = acc[mi][ni][2] + bz0, v11 = acc[mi][ni][3] + bz1;
            if (GELU) {   // h feeds GEMM2's A: round to tf32 here
                v00 = tf32r(gelu_tanh(v00)); v01 = tf32r(gelu_tanh(v01));
                v10 = tf32r(gelu_tanh(v10)); v11 = tf32r(gelu_tanh(v11));
            }
            *(float2*)(C + (size_t)row * N + col)       = make_float2(v00, v01);
            *(float2*)(C + (size_t)(row + 8) * N + col) = make_float2(v10, v11);
        }
    }
}

// ---------------- launch ----------------
extern "C" void kernel_launch(void* const* d_in, const int* in_sizes, int n_in,
                              void* d_out, int out_size)
{
    const float* x  = (const float*)d_in[0];
    const float* w1 = (const float*)d_in[2];
    const float* b1 = (const float*)d_in[3];
    const float* w2 = (const float*)d_in[4];
    const float* b2 = (const float*)d_in[5];
    float* y = (float*)d_out;

    float *xr, *h, *w1t, *w2t;
    cudaGetSymbolAddress((void**)&xr,  g_x);
    cudaGetSymbolAddress((void**)&h,   g_h);
    cudaGetSymbolAddress((void**)&w1t, g_w1t);
    cudaGetSymbolAddress((void**)&w2t, g_w2t);

    const int smem_bytes = STAGES * (BM * STRIDE + BN * STRIDE) * (int)sizeof(float);
    cudaFuncSetAttribute((const void*)moe_gemm<true>,
                         cudaFuncAttributeMaxDynamicSharedMemorySize, smem_bytes);
    cudaFuncSetAttribute((const void*)moe_gemm<false>,
                         cudaFuncAttributeMaxDynamicSharedMemorySize, smem_bytes);

    // pre-passes: round x; transpose + round weights to K-major [N, K]
    {
        int n4 = NE * TPE * DMODEL / 4;
        round_x_k<<<(n4 + 255) / 256, 256>>>(x, xr, n4);
        dim3 t1(DFF / 32, DMODEL / 32, NE);     // w1 [D,F] -> w1t [F,D]
        transpose_round_k<<<t1, 256>>>(w1, w1t, DMODEL, DFF);
        dim3 t2(DMODEL / 32, DFF / 32, NE);     // w2 [F,D] -> w2t [D,F]
        transpose_round_k<<<t2, 256>>>(w2, w2t, DFF, DMODEL);
    }

    dim3 blk(NT);
    // GEMM1: h = gelu(x @ w1 + b1)   per expert 2048x1024 @ 1024x4096
    dim3 g1(DFF / BN, TPE / BM, NE);
    moe_gemm<true><<<g1, blk, smem_bytes>>>(xr, w1t, b1, h, DMODEL, DFF);
    // GEMM2: y = h @ w2 + b2         per expert 2048x4096 @ 4096x1024
    dim3 g2(DMODEL / BN, TPE / BM, NE);
    moe_gemm<false><<<g2, blk, smem_bytes>>>(h, w2t, b2, y, DFF, DMODEL);
}